// round 3
// baseline (speedup 1.0000x reference)
#include <cuda_runtime.h>

// ---------------------------------------------------------------------------
// DRQN fused pipeline for GB300 (sm_103a), fp32 with FFMA2 (fma.rn.f32x2).
//
//   hvec   = W_hh @ h + b_ih + b_hh                      (vector, 2048)
//   x      = relu([obs|act] @ W1^T + b1)                 (GEMM1, fused concat)
//   gates  = x @ W_ih^T + hvec  -> LSTM cell epilogue    (GEMM2, gate-interleaved)
//   q      = h_new @ W2^T + b2                           (GEMM3)
//
// Output layout: [ q (B*32) | h_new[B-1] (512) | c_new[B-1] (512) ]
// ---------------------------------------------------------------------------

#define B_ROWS 32768
#define OBS    512
#define ACT    32
#define KIN    544      // OBS + ACT
#define EMB    512
#define HID    512
#define NQ     32

// Scratch (device globals: no runtime allocation allowed)
__device__ float g_x[(size_t)B_ROWS * EMB];     // 64 MB
__device__ float g_h[(size_t)B_ROWS * HID];     // 64 MB
__device__ float g_hvec[4 * HID];               // 8 KB

typedef unsigned long long ull;

__device__ __forceinline__ ull pack2(float lo, float hi) {
    ull r; asm("mov.b64 %0, {%1,%2};" : "=l"(r) : "f"(lo), "f"(hi)); return r;
}
__device__ __forceinline__ void unpack2(ull v, float& lo, float& hi) {
    asm("mov.b64 {%0,%1}, %2;" : "=f"(lo), "=f"(hi) : "l"(v));
}
// Packed dual-FMA: (a.lo*b.lo+c.lo, a.hi*b.hi+c.hi). sm_100+ only; ptxas never
// auto-fuses this from C++ — must come from PTX.
__device__ __forceinline__ ull ffma2(ull a, ull b, ull c) {
    ull d; asm("fma.rn.f32x2 %0, %1, %2, %3;" : "=l"(d) : "l"(a), "l"(b), "l"(c)); return d;
}

// Accurate-enough transcendentals (~1e-6 abs): do NOT use tanh.approx (5e-4
// abs error would threaten the 1e-3 rel-err gate).
__device__ __forceinline__ float sigmoidf_(float x) {
    return __fdividef(1.f, 1.f + __expf(-x));
}
__device__ __forceinline__ float tanhf_(float x) {
    // 2*sigmoid(2x)-1; robust for |x| large (expf saturates to 0 or +inf -> +/-1)
    return __fdividef(2.f, 1.f + __expf(-2.f * x)) - 1.f;
}

// ---------------------------------------------------------------------------
// K0: hvec[n] = dot(W_hh[n,:], h) + b_ih[n] + b_hh[n], n in [0,2048)
// One warp per output. 2048 warps total.
// ---------------------------------------------------------------------------
__global__ void __launch_bounds__(256) hvec_kernel(
    const float* __restrict__ Whh, const float* __restrict__ h,
    const float* __restrict__ bih, const float* __restrict__ bhh)
{
    int w    = (blockIdx.x * blockDim.x + threadIdx.x) >> 5;
    int lane = threadIdx.x & 31;
    if (w >= 4 * HID) return;
    const float* row = Whh + (size_t)w * HID;
    float s = 0.f;
    #pragma unroll
    for (int k = 0; k < HID; k += 32) s += row[k + lane] * h[k + lane];
    #pragma unroll
    for (int o = 16; o > 0; o >>= 1) s += __shfl_xor_sync(0xffffffffu, s, o);
    if (lane == 0) g_hvec[w] = s + bih[w] + bhh[w];
}

// ---------------------------------------------------------------------------
// K1: x = relu([obs|act] @ W1^T + b1).  BM=BN=128, BK=16, 256 thr, 8x8/thr.
// ---------------------------------------------------------------------------
__global__ void __launch_bounds__(256) mlp1_kernel(
    const float* __restrict__ obs, const float* __restrict__ act,
    const float* __restrict__ W1,  const float* __restrict__ b1)
{
    __shared__ float As[16][128];
    __shared__ float Ws[16][128];
    const int tid = threadIdx.x;
    const int ty = tid >> 4, tx = tid & 15;
    const int rowBase = blockIdx.x * 128;
    const int colBase = blockIdx.y * 128;
    const int lr = tid >> 2;            // 0..63
    const int lc = (tid & 3) * 4;       // 0,4,8,12

    ull acc[4][8];
    #pragma unroll
    for (int i = 0; i < 4; i++)
        #pragma unroll
        for (int j = 0; j < 8; j++) acc[i][j] = 0ULL;

    for (int k0 = 0; k0 < KIN; k0 += 16) {
        #pragma unroll
        for (int hh = 0; hh < 2; hh++) {
            int r  = lr + hh * 64;
            int kg = k0 + lc;
            float4 av;
            if (kg < OBS) av = *(const float4*)(obs + (size_t)(rowBase + r) * OBS + kg);
            else          av = *(const float4*)(act + (size_t)(rowBase + r) * ACT + (kg - OBS));
            As[lc + 0][r] = av.x; As[lc + 1][r] = av.y;
            As[lc + 2][r] = av.z; As[lc + 3][r] = av.w;
            float4 wv = *(const float4*)(W1 + (size_t)(colBase + r) * KIN + kg);
            Ws[lc + 0][r] = wv.x; Ws[lc + 1][r] = wv.y;
            Ws[lc + 2][r] = wv.z; Ws[lc + 3][r] = wv.w;
        }
        __syncthreads();
        #pragma unroll
        for (int kk = 0; kk < 16; kk++) {
            ulonglong2 a01 = *(const ulonglong2*)&As[kk][ty * 8];
            ulonglong2 a23 = *(const ulonglong2*)&As[kk][ty * 8 + 4];
            ull a2v[4] = {a01.x, a01.y, a23.x, a23.y};
            float4 b0  = *(const float4*)&Ws[kk][tx * 8];
            float4 b1v = *(const float4*)&Ws[kk][tx * 8 + 4];
            float bb[8] = {b0.x, b0.y, b0.z, b0.w, b1v.x, b1v.y, b1v.z, b1v.w};
            #pragma unroll
            for (int j = 0; j < 8; j++) {
                ull bd = pack2(bb[j], bb[j]);
                #pragma unroll
                for (int i = 0; i < 4; i++) acc[i][j] = ffma2(a2v[i], bd, acc[i][j]);
            }
        }
        __syncthreads();
    }

    float vals[8][8];
    #pragma unroll
    for (int i = 0; i < 4; i++)
        #pragma unroll
        for (int j = 0; j < 8; j++) unpack2(acc[i][j], vals[2 * i][j], vals[2 * i + 1][j]);

    #pragma unroll
    for (int rr = 0; rr < 8; rr++) {
        int grow = rowBase + ty * 8 + rr;
        int gcol = colBase + tx * 8;
        float o[8];
        #pragma unroll
        for (int j = 0; j < 8; j++) {
            float v = vals[rr][j] + b1[gcol + j];
            o[j] = v > 0.f ? v : 0.f;
        }
        float* dst = g_x + (size_t)grow * EMB + gcol;
        *(float4*)(dst)     = make_float4(o[0], o[1], o[2], o[3]);
        *(float4*)(dst + 4) = make_float4(o[4], o[5], o[6], o[7]);
    }
}

// ---------------------------------------------------------------------------
// K2: gate-interleaved GEMM2 + LSTM epilogue.
// Block covers 128 batch rows x 32 hid cols (= 128 gate columns).
// Tile column r (0..127)  <->  W_ih row = 512*(r%4) + hb + r/4, so each
// thread's 8 contiguous columns = 2 hid indices x all 4 gates {i,f,g,o}.
// ---------------------------------------------------------------------------
__global__ void __launch_bounds__(256) lstm_kernel(
    const float* __restrict__ Wih, const float* __restrict__ cell,
    float* __restrict__ out)
{
    __shared__ float As[16][128];
    __shared__ float Ws[16][128];
    const int tid = threadIdx.x;
    const int ty = tid >> 4, tx = tid & 15;
    const int rowBase = blockIdx.x * 128;
    const int hb = blockIdx.y * 32;
    const int lr = tid >> 2;
    const int lc = (tid & 3) * 4;

    ull acc[4][8];
    #pragma unroll
    for (int i = 0; i < 4; i++)
        #pragma unroll
        for (int j = 0; j < 8; j++) acc[i][j] = 0ULL;

    for (int k0 = 0; k0 < EMB; k0 += 16) {
        #pragma unroll
        for (int hh = 0; hh < 2; hh++) {
            int r = lr + hh * 64;
            float4 av = *(const float4*)(g_x + (size_t)(rowBase + r) * EMB + k0 + lc);
            As[lc + 0][r] = av.x; As[lc + 1][r] = av.y;
            As[lc + 2][r] = av.z; As[lc + 3][r] = av.w;
            int wrow = ((r & 3) << 9) + hb + (r >> 2);   // 512*gate + hid
            float4 wv = *(const float4*)(Wih + (size_t)wrow * EMB + k0 + lc);
            Ws[lc + 0][r] = wv.x; Ws[lc + 1][r] = wv.y;
            Ws[lc + 2][r] = wv.z; Ws[lc + 3][r] = wv.w;
        }
        __syncthreads();
        #pragma unroll
        for (int kk = 0; kk < 16; kk++) {
            ulonglong2 a01 = *(const ulonglong2*)&As[kk][ty * 8];
            ulonglong2 a23 = *(const ulonglong2*)&As[kk][ty * 8 + 4];
            ull a2v[4] = {a01.x, a01.y, a23.x, a23.y};
            float4 b0  = *(const float4*)&Ws[kk][tx * 8];
            float4 b1v = *(const float4*)&Ws[kk][tx * 8 + 4];
            float bb[8] = {b0.x, b0.y, b0.z, b0.w, b1v.x, b1v.y, b1v.z, b1v.w};
            #pragma unroll
            for (int j = 0; j < 8; j++) {
                ull bd = pack2(bb[j], bb[j]);
                #pragma unroll
                for (int i = 0; i < 4; i++) acc[i][j] = ffma2(a2v[i], bd, acc[i][j]);
            }
        }
        __syncthreads();
    }

    float vals[8][8];
    #pragma unroll
    for (int i = 0; i < 4; i++)
        #pragma unroll
        for (int j = 0; j < 8; j++) unpack2(acc[i][j], vals[2 * i][j], vals[2 * i + 1][j]);

    #pragma unroll
    for (int rr = 0; rr < 8; rr++) {
        int grow = rowBase + ty * 8 + rr;
        #pragma unroll
        for (int jh = 0; jh < 2; jh++) {
            int hid = hb + tx * 2 + jh;            // global hid index
            // column j = jh*4 + gate; gate order i,f,g,o (torch LSTMCell)
            float iv = sigmoidf_(vals[rr][jh * 4 + 0] + g_hvec[hid]);
            float fv = sigmoidf_(vals[rr][jh * 4 + 1] + g_hvec[HID + hid]);
            float gv = tanhf_   (vals[rr][jh * 4 + 2] + g_hvec[2 * HID + hid]);
            float ov = sigmoidf_(vals[rr][jh * 4 + 3] + g_hvec[3 * HID + hid]);
            float c = fv * cell[hid] + iv * gv;
            float h = ov * tanhf_(c);
            g_h[(size_t)grow * HID + hid] = h;
            if (grow == B_ROWS - 1) {
                out[(size_t)B_ROWS * NQ + hid]       = h;   // h_new[-1]
                out[(size_t)B_ROWS * NQ + HID + hid] = c;   // c_new[-1]
            }
        }
    }
}

// ---------------------------------------------------------------------------
// K3: q = h_new @ W2^T + b2.  Block = 32 rows x 32 cols, chunked K=128.
// ---------------------------------------------------------------------------
__global__ void __launch_bounds__(256) q_kernel(
    const float* __restrict__ W2, const float* __restrict__ b2,
    float* __restrict__ q)
{
    __shared__ float sW[32][129];   // pad -> conflict-free column reads
    __shared__ float sH[32][128];
    const int tid = threadIdx.x;
    const int rowBase = blockIdx.x * 32;
    const int c  = tid & 31;
    const int rq = tid >> 5;        // 0..7
    const int lwr = tid >> 3;       // 0..31
    const int lwc = (tid & 7) * 16; // 0..112

    float acc[4] = {0.f, 0.f, 0.f, 0.f};

    for (int k0 = 0; k0 < HID; k0 += 128) {
        #pragma unroll
        for (int i = 0; i < 4; i++) {
            float4 wv = *(const float4*)(W2 + (size_t)lwr * HID + k0 + lwc + i * 4);
            sW[lwr][lwc + i * 4 + 0] = wv.x; sW[lwr][lwc + i * 4 + 1] = wv.y;
            sW[lwr][lwc + i * 4 + 2] = wv.z; sW[lwr][lwc + i * 4 + 3] = wv.w;
            float4 hv = *(const float4*)(g_h + (size_t)(rowBase + lwr) * HID + k0 + lwc + i * 4);
            sH[lwr][lwc + i * 4 + 0] = hv.x; sH[lwr][lwc + i * 4 + 1] = hv.y;
            sH[lwr][lwc + i * 4 + 2] = hv.z; sH[lwr][lwc + i * 4 + 3] = hv.w;
        }
        __syncthreads();
        #pragma unroll 8
        for (int kk = 0; kk < 128; kk++) {
            float w = sW[c][kk];
            #pragma unroll
            for (int r = 0; r < 4; r++) acc[r] += sH[rq + r * 8][kk] * w;
        }
        __syncthreads();
    }
    #pragma unroll
    for (int r = 0; r < 4; r++)
        q[(size_t)(rowBase + rq + r * 8) * NQ + c] = acc[r] + b2[c];
}

// ---------------------------------------------------------------------------
// Launch. Input order per metadata: observation, prev_action, hidden_state,
// cell_state, W1, b1, W_ih, b_ih, W_hh, b_hh, W2, b2.
// ---------------------------------------------------------------------------
extern "C" void kernel_launch(void* const* d_in, const int* in_sizes, int n_in,
                              void* d_out, int out_size)
{
    const float* obs  = (const float*)d_in[0];
    const float* act  = (const float*)d_in[1];
    const float* hst  = (const float*)d_in[2];
    const float* cst  = (const float*)d_in[3];
    const float* W1   = (const float*)d_in[4];
    const float* b1   = (const float*)d_in[5];
    const float* Wih  = (const float*)d_in[6];
    const float* bih  = (const float*)d_in[7];
    const float* Whh  = (const float*)d_in[8];
    const float* bhh  = (const float*)d_in[9];
    const float* W2   = (const float*)d_in[10];
    const float* b2   = (const float*)d_in[11];
    float* out = (float*)d_out;

    hvec_kernel<<<256, 256>>>(Whh, hst, bih, bhh);
    mlp1_kernel<<<dim3(B_ROWS / 128, EMB / 128), 256>>>(obs, act, W1, b1);
    lstm_kernel<<<dim3(B_ROWS / 128, HID / 32), 256>>>(Wih, cst, out);
    q_kernel<<<B_ROWS / 32, 256>>>(W2, b2, out);
}

// round 4
// speedup vs baseline: 1.0003x; 1.0003x over previous
#include <cuda_runtime.h>

// ---------------------------------------------------------------------------
// DRQN fused pipeline for GB300 (sm_103a), fp32 with FFMA2 (fma.rn.f32x2).
//
//   hvec   = W_hh @ h + b_ih + b_hh                      (vector, 2048)
//   x      = relu([obs|act] @ W1^T + b1)                 (GEMM1, fused concat)
//   gates  = x @ W_ih^T + hvec  -> LSTM cell epilogue    (GEMM2, gate-interleaved)
//   q      = h_new @ W2^T + b2                           (GEMM3)
//
// Output layout: [ q (B*32) | h_new[B-1] (512) | c_new[B-1] (512) ]
// ---------------------------------------------------------------------------

#define B_ROWS 32768
#define OBS    512
#define ACT    32
#define KIN    544      // OBS + ACT
#define EMB    512
#define HID    512
#define NQ     32

// Scratch (device globals: no runtime allocation allowed)
__device__ float g_x[(size_t)B_ROWS * EMB];     // 64 MB
__device__ float g_h[(size_t)B_ROWS * HID];     // 64 MB
__device__ float g_hvec[4 * HID];               // 8 KB

typedef unsigned long long ull;

__device__ __forceinline__ ull pack2(float lo, float hi) {
    ull r; asm("mov.b64 %0, {%1,%2};" : "=l"(r) : "f"(lo), "f"(hi)); return r;
}
__device__ __forceinline__ void unpack2(ull v, float& lo, float& hi) {
    asm("mov.b64 {%0,%1}, %2;" : "=f"(lo), "=f"(hi) : "l"(v));
}
// Packed dual-FMA: (a.lo*b.lo+c.lo, a.hi*b.hi+c.hi). sm_100+ only; ptxas never
// auto-fuses this from C++ — must come from PTX.
__device__ __forceinline__ ull ffma2(ull a, ull b, ull c) {
    ull d; asm("fma.rn.f32x2 %0, %1, %2, %3;" : "=l"(d) : "l"(a), "l"(b), "l"(c)); return d;
}

// Accurate-enough transcendentals (~1e-6 abs): do NOT use tanh.approx (5e-4
// abs error would threaten the 1e-3 rel-err gate).
__device__ __forceinline__ float sigmoidf_(float x) {
    return __fdividef(1.f, 1.f + __expf(-x));
}
__device__ __forceinline__ float tanhf_(float x) {
    // 2*sigmoid(2x)-1; robust for |x| large (expf saturates to 0 or +inf -> +/-1)
    return __fdividef(2.f, 1.f + __expf(-2.f * x)) - 1.f;
}

// ---------------------------------------------------------------------------
// K0: hvec[n] = dot(W_hh[n,:], h) + b_ih[n] + b_hh[n], n in [0,2048)
// One warp per output. 2048 warps total.
// ---------------------------------------------------------------------------
__global__ void __launch_bounds__(256) hvec_kernel(
    const float* __restrict__ Whh, const float* __restrict__ h,
    const float* __restrict__ bih, const float* __restrict__ bhh)
{
    int w    = (blockIdx.x * blockDim.x + threadIdx.x) >> 5;
    int lane = threadIdx.x & 31;
    if (w >= 4 * HID) return;
    const float* row = Whh + (size_t)w * HID;
    float s = 0.f;
    #pragma unroll
    for (int k = 0; k < HID; k += 32) s += row[k + lane] * h[k + lane];
    #pragma unroll
    for (int o = 16; o > 0; o >>= 1) s += __shfl_xor_sync(0xffffffffu, s, o);
    if (lane == 0) g_hvec[w] = s + bih[w] + bhh[w];
}

// ---------------------------------------------------------------------------
// K1: x = relu([obs|act] @ W1^T + b1).  BM=BN=128, BK=16, 256 thr, 8x8/thr.
// ---------------------------------------------------------------------------
__global__ void __launch_bounds__(256) mlp1_kernel(
    const float* __restrict__ obs, const float* __restrict__ act,
    const float* __restrict__ W1,  const float* __restrict__ b1)
{
    __shared__ float As[16][128];
    __shared__ float Ws[16][128];
    const int tid = threadIdx.x;
    const int ty = tid >> 4, tx = tid & 15;
    const int rowBase = blockIdx.x * 128;
    const int colBase = blockIdx.y * 128;
    const int lr = tid >> 2;            // 0..63
    const int lc = (tid & 3) * 4;       // 0,4,8,12

    ull acc[4][8];
    #pragma unroll
    for (int i = 0; i < 4; i++)
        #pragma unroll
        for (int j = 0; j < 8; j++) acc[i][j] = 0ULL;

    for (int k0 = 0; k0 < KIN; k0 += 16) {
        #pragma unroll
        for (int hh = 0; hh < 2; hh++) {
            int r  = lr + hh * 64;
            int kg = k0 + lc;
            float4 av;
            if (kg < OBS) av = *(const float4*)(obs + (size_t)(rowBase + r) * OBS + kg);
            else          av = *(const float4*)(act + (size_t)(rowBase + r) * ACT + (kg - OBS));
            As[lc + 0][r] = av.x; As[lc + 1][r] = av.y;
            As[lc + 2][r] = av.z; As[lc + 3][r] = av.w;
            float4 wv = *(const float4*)(W1 + (size_t)(colBase + r) * KIN + kg);
            Ws[lc + 0][r] = wv.x; Ws[lc + 1][r] = wv.y;
            Ws[lc + 2][r] = wv.z; Ws[lc + 3][r] = wv.w;
        }
        __syncthreads();
        #pragma unroll
        for (int kk = 0; kk < 16; kk++) {
            ulonglong2 a01 = *(const ulonglong2*)&As[kk][ty * 8];
            ulonglong2 a23 = *(const ulonglong2*)&As[kk][ty * 8 + 4];
            ull a2v[4] = {a01.x, a01.y, a23.x, a23.y};
            float4 b0  = *(const float4*)&Ws[kk][tx * 8];
            float4 b1v = *(const float4*)&Ws[kk][tx * 8 + 4];
            float bb[8] = {b0.x, b0.y, b0.z, b0.w, b1v.x, b1v.y, b1v.z, b1v.w};
            #pragma unroll
            for (int j = 0; j < 8; j++) {
                ull bd = pack2(bb[j], bb[j]);
                #pragma unroll
                for (int i = 0; i < 4; i++) acc[i][j] = ffma2(a2v[i], bd, acc[i][j]);
            }
        }
        __syncthreads();
    }

    float vals[8][8];
    #pragma unroll
    for (int i = 0; i < 4; i++)
        #pragma unroll
        for (int j = 0; j < 8; j++) unpack2(acc[i][j], vals[2 * i][j], vals[2 * i + 1][j]);

    #pragma unroll
    for (int rr = 0; rr < 8; rr++) {
        int grow = rowBase + ty * 8 + rr;
        int gcol = colBase + tx * 8;
        float o[8];
        #pragma unroll
        for (int j = 0; j < 8; j++) {
            float v = vals[rr][j] + b1[gcol + j];
            o[j] = v > 0.f ? v : 0.f;
        }
        float* dst = g_x + (size_t)grow * EMB + gcol;
        *(float4*)(dst)     = make_float4(o[0], o[1], o[2], o[3]);
        *(float4*)(dst + 4) = make_float4(o[4], o[5], o[6], o[7]);
    }
}

// ---------------------------------------------------------------------------
// K2: gate-interleaved GEMM2 + LSTM epilogue.
// Block covers 128 batch rows x 32 hid cols (= 128 gate columns).
// Tile column r (0..127)  <->  W_ih row = 512*(r%4) + hb + r/4, so each
// thread's 8 contiguous columns = 2 hid indices x all 4 gates {i,f,g,o}.
// ---------------------------------------------------------------------------
__global__ void __launch_bounds__(256) lstm_kernel(
    const float* __restrict__ Wih, const float* __restrict__ cell,
    float* __restrict__ out)
{
    __shared__ float As[16][128];
    __shared__ float Ws[16][128];
    const int tid = threadIdx.x;
    const int ty = tid >> 4, tx = tid & 15;
    const int rowBase = blockIdx.x * 128;
    const int hb = blockIdx.y * 32;
    const int lr = tid >> 2;
    const int lc = (tid & 3) * 4;

    ull acc[4][8];
    #pragma unroll
    for (int i = 0; i < 4; i++)
        #pragma unroll
        for (int j = 0; j < 8; j++) acc[i][j] = 0ULL;

    for (int k0 = 0; k0 < EMB; k0 += 16) {
        #pragma unroll
        for (int hh = 0; hh < 2; hh++) {
            int r = lr + hh * 64;
            float4 av = *(const float4*)(g_x + (size_t)(rowBase + r) * EMB + k0 + lc);
            As[lc + 0][r] = av.x; As[lc + 1][r] = av.y;
            As[lc + 2][r] = av.z; As[lc + 3][r] = av.w;
            int wrow = ((r & 3) << 9) + hb + (r >> 2);   // 512*gate + hid
            float4 wv = *(const float4*)(Wih + (size_t)wrow * EMB + k0 + lc);
            Ws[lc + 0][r] = wv.x; Ws[lc + 1][r] = wv.y;
            Ws[lc + 2][r] = wv.z; Ws[lc + 3][r] = wv.w;
        }
        __syncthreads();
        #pragma unroll
        for (int kk = 0; kk < 16; kk++) {
            ulonglong2 a01 = *(const ulonglong2*)&As[kk][ty * 8];
            ulonglong2 a23 = *(const ulonglong2*)&As[kk][ty * 8 + 4];
            ull a2v[4] = {a01.x, a01.y, a23.x, a23.y};
            float4 b0  = *(const float4*)&Ws[kk][tx * 8];
            float4 b1v = *(const float4*)&Ws[kk][tx * 8 + 4];
            float bb[8] = {b0.x, b0.y, b0.z, b0.w, b1v.x, b1v.y, b1v.z, b1v.w};
            #pragma unroll
            for (int j = 0; j < 8; j++) {
                ull bd = pack2(bb[j], bb[j]);
                #pragma unroll
                for (int i = 0; i < 4; i++) acc[i][j] = ffma2(a2v[i], bd, acc[i][j]);
            }
        }
        __syncthreads();
    }

    float vals[8][8];
    #pragma unroll
    for (int i = 0; i < 4; i++)
        #pragma unroll
        for (int j = 0; j < 8; j++) unpack2(acc[i][j], vals[2 * i][j], vals[2 * i + 1][j]);

    #pragma unroll
    for (int rr = 0; rr < 8; rr++) {
        int grow = rowBase + ty * 8 + rr;
        #pragma unroll
        for (int jh = 0; jh < 2; jh++) {
            int hid = hb + tx * 2 + jh;            // global hid index
            // column j = jh*4 + gate; gate order i,f,g,o (torch LSTMCell)
            float iv = sigmoidf_(vals[rr][jh * 4 + 0] + g_hvec[hid]);
            float fv = sigmoidf_(vals[rr][jh * 4 + 1] + g_hvec[HID + hid]);
            float gv = tanhf_   (vals[rr][jh * 4 + 2] + g_hvec[2 * HID + hid]);
            float ov = sigmoidf_(vals[rr][jh * 4 + 3] + g_hvec[3 * HID + hid]);
            float c = fv * cell[hid] + iv * gv;
            float h = ov * tanhf_(c);
            g_h[(size_t)grow * HID + hid] = h;
            if (grow == B_ROWS - 1) {
                out[(size_t)B_ROWS * NQ + hid]       = h;   // h_new[-1]
                out[(size_t)B_ROWS * NQ + HID + hid] = c;   // c_new[-1]
            }
        }
    }
}

// ---------------------------------------------------------------------------
// K3: q = h_new @ W2^T + b2.  Block = 32 rows x 32 cols, chunked K=128.
// ---------------------------------------------------------------------------
__global__ void __launch_bounds__(256) q_kernel(
    const float* __restrict__ W2, const float* __restrict__ b2,
    float* __restrict__ q)
{
    __shared__ float sW[32][129];   // pad -> conflict-free column reads
    __shared__ float sH[32][128];
    const int tid = threadIdx.x;
    const int rowBase = blockIdx.x * 32;
    const int c  = tid & 31;
    const int rq = tid >> 5;        // 0..7
    const int lwr = tid >> 3;       // 0..31
    const int lwc = (tid & 7) * 16; // 0..112

    float acc[4] = {0.f, 0.f, 0.f, 0.f};

    for (int k0 = 0; k0 < HID; k0 += 128) {
        #pragma unroll
        for (int i = 0; i < 4; i++) {
            float4 wv = *(const float4*)(W2 + (size_t)lwr * HID + k0 + lwc + i * 4);
            sW[lwr][lwc + i * 4 + 0] = wv.x; sW[lwr][lwc + i * 4 + 1] = wv.y;
            sW[lwr][lwc + i * 4 + 2] = wv.z; sW[lwr][lwc + i * 4 + 3] = wv.w;
            float4 hv = *(const float4*)(g_h + (size_t)(rowBase + lwr) * HID + k0 + lwc + i * 4);
            sH[lwr][lwc + i * 4 + 0] = hv.x; sH[lwr][lwc + i * 4 + 1] = hv.y;
            sH[lwr][lwc + i * 4 + 2] = hv.z; sH[lwr][lwc + i * 4 + 3] = hv.w;
        }
        __syncthreads();
        #pragma unroll 8
        for (int kk = 0; kk < 128; kk++) {
            float w = sW[c][kk];
            #pragma unroll
            for (int r = 0; r < 4; r++) acc[r] += sH[rq + r * 8][kk] * w;
        }
        __syncthreads();
    }
    #pragma unroll
    for (int r = 0; r < 4; r++)
        q[(size_t)(rowBase + rq + r * 8) * NQ + c] = acc[r] + b2[c];
}

// ---------------------------------------------------------------------------
// Launch. Input order per metadata: observation, prev_action, hidden_state,
// cell_state, W1, b1, W_ih, b_ih, W_hh, b_hh, W2, b2.
// ---------------------------------------------------------------------------
extern "C" void kernel_launch(void* const* d_in, const int* in_sizes, int n_in,
                              void* d_out, int out_size)
{
    const float* obs  = (const float*)d_in[0];
    const float* act  = (const float*)d_in[1];
    const float* hst  = (const float*)d_in[2];
    const float* cst  = (const float*)d_in[3];
    const float* W1   = (const float*)d_in[4];
    const float* b1   = (const float*)d_in[5];
    const float* Wih  = (const float*)d_in[6];
    const float* bih  = (const float*)d_in[7];
    const float* Whh  = (const float*)d_in[8];
    const float* bhh  = (const float*)d_in[9];
    const float* W2   = (const float*)d_in[10];
    const float* b2   = (const float*)d_in[11];
    float* out = (float*)d_out;

    hvec_kernel<<<256, 256>>>(Whh, hst, bih, bhh);
    mlp1_kernel<<<dim3(B_ROWS / 128, EMB / 128), 256>>>(obs, act, W1, b1);
    lstm_kernel<<<dim3(B_ROWS / 128, HID / 32), 256>>>(Wih, cst, out);
    q_kernel<<<B_ROWS / 32, 256>>>(W2, b2, out);
}

// round 5
// speedup vs baseline: 1.0013x; 1.0010x over previous
#include <cuda_runtime.h>

// ---------------------------------------------------------------------------
// DRQN fused pipeline for GB300 (sm_103a), fp32 with FFMA2 (fma.rn.f32x2).
//
//   hvec   = W_hh @ h + b_ih + b_hh                      (vector, 2048)
//   x      = relu([obs|act] @ W1^T + b1)                 (GEMM1, fused concat)
//   gates  = x @ W_ih^T + hvec  -> LSTM cell epilogue    (GEMM2, gate-interleaved)
//   q      = h_new @ W2^T + b2                           (GEMM3)
//
// Output layout: [ q (B*32) | h_new[B-1] (512) | c_new[B-1] (512) ]
// ---------------------------------------------------------------------------

#define B_ROWS 32768
#define OBS    512
#define ACT    32
#define KIN    544      // OBS + ACT
#define EMB    512
#define HID    512
#define NQ     32

// Scratch (device globals: no runtime allocation allowed)
__device__ float g_x[(size_t)B_ROWS * EMB];     // 64 MB
__device__ float g_h[(size_t)B_ROWS * HID];     // 64 MB
__device__ float g_hvec[4 * HID];               // 8 KB

typedef unsigned long long ull;

__device__ __forceinline__ ull pack2(float lo, float hi) {
    ull r; asm("mov.b64 %0, {%1,%2};" : "=l"(r) : "f"(lo), "f"(hi)); return r;
}
__device__ __forceinline__ void unpack2(ull v, float& lo, float& hi) {
    asm("mov.b64 {%0,%1}, %2;" : "=f"(lo), "=f"(hi) : "l"(v));
}
// Packed dual-FMA: (a.lo*b.lo+c.lo, a.hi*b.hi+c.hi). sm_100+ only; ptxas never
// auto-fuses this from C++ — must come from PTX.
__device__ __forceinline__ ull ffma2(ull a, ull b, ull c) {
    ull d; asm("fma.rn.f32x2 %0, %1, %2, %3;" : "=l"(d) : "l"(a), "l"(b), "l"(c)); return d;
}

// Accurate-enough transcendentals (~1e-6 abs): do NOT use tanh.approx (5e-4
// abs error would threaten the 1e-3 rel-err gate).
__device__ __forceinline__ float sigmoidf_(float x) {
    return __fdividef(1.f, 1.f + __expf(-x));
}
__device__ __forceinline__ float tanhf_(float x) {
    // 2*sigmoid(2x)-1; robust for |x| large (expf saturates to 0 or +inf -> +/-1)
    return __fdividef(2.f, 1.f + __expf(-2.f * x)) - 1.f;
}

// ---------------------------------------------------------------------------
// K0: hvec[n] = dot(W_hh[n,:], h) + b_ih[n] + b_hh[n], n in [0,2048)
// One warp per output. 2048 warps total.
// ---------------------------------------------------------------------------
__global__ void __launch_bounds__(256) hvec_kernel(
    const float* __restrict__ Whh, const float* __restrict__ h,
    const float* __restrict__ bih, const float* __restrict__ bhh)
{
    int w    = (blockIdx.x * blockDim.x + threadIdx.x) >> 5;
    int lane = threadIdx.x & 31;
    if (w >= 4 * HID) return;
    const float* row = Whh + (size_t)w * HID;
    float s = 0.f;
    #pragma unroll
    for (int k = 0; k < HID; k += 32) s += row[k + lane] * h[k + lane];
    #pragma unroll
    for (int o = 16; o > 0; o >>= 1) s += __shfl_xor_sync(0xffffffffu, s, o);
    if (lane == 0) g_hvec[w] = s + bih[w] + bhh[w];
}

// ---------------------------------------------------------------------------
// K1: x = relu([obs|act] @ W1^T + b1).  BM=BN=128, BK=16, 256 thr, 8x8/thr.
// ---------------------------------------------------------------------------
__global__ void __launch_bounds__(256) mlp1_kernel(
    const float* __restrict__ obs, const float* __restrict__ act,
    const float* __restrict__ W1,  const float* __restrict__ b1)
{
    __shared__ float As[16][128];
    __shared__ float Ws[16][128];
    const int tid = threadIdx.x;
    const int ty = tid >> 4, tx = tid & 15;
    const int rowBase = blockIdx.x * 128;
    const int colBase = blockIdx.y * 128;
    const int lr = tid >> 2;            // 0..63
    const int lc = (tid & 3) * 4;       // 0,4,8,12

    ull acc[4][8];
    #pragma unroll
    for (int i = 0; i < 4; i++)
        #pragma unroll
        for (int j = 0; j < 8; j++) acc[i][j] = 0ULL;

    for (int k0 = 0; k0 < KIN; k0 += 16) {
        #pragma unroll
        for (int hh = 0; hh < 2; hh++) {
            int r  = lr + hh * 64;
            int kg = k0 + lc;
            float4 av;
            if (kg < OBS) av = *(const float4*)(obs + (size_t)(rowBase + r) * OBS + kg);
            else          av = *(const float4*)(act + (size_t)(rowBase + r) * ACT + (kg - OBS));
            As[lc + 0][r] = av.x; As[lc + 1][r] = av.y;
            As[lc + 2][r] = av.z; As[lc + 3][r] = av.w;
            float4 wv = *(const float4*)(W1 + (size_t)(colBase + r) * KIN + kg);
            Ws[lc + 0][r] = wv.x; Ws[lc + 1][r] = wv.y;
            Ws[lc + 2][r] = wv.z; Ws[lc + 3][r] = wv.w;
        }
        __syncthreads();
        #pragma unroll
        for (int kk = 0; kk < 16; kk++) {
            ulonglong2 a01 = *(const ulonglong2*)&As[kk][ty * 8];
            ulonglong2 a23 = *(const ulonglong2*)&As[kk][ty * 8 + 4];
            ull a2v[4] = {a01.x, a01.y, a23.x, a23.y};
            float4 b0  = *(const float4*)&Ws[kk][tx * 8];
            float4 b1v = *(const float4*)&Ws[kk][tx * 8 + 4];
            float bb[8] = {b0.x, b0.y, b0.z, b0.w, b1v.x, b1v.y, b1v.z, b1v.w};
            #pragma unroll
            for (int j = 0; j < 8; j++) {
                ull bd = pack2(bb[j], bb[j]);
                #pragma unroll
                for (int i = 0; i < 4; i++) acc[i][j] = ffma2(a2v[i], bd, acc[i][j]);
            }
        }
        __syncthreads();
    }

    float vals[8][8];
    #pragma unroll
    for (int i = 0; i < 4; i++)
        #pragma unroll
        for (int j = 0; j < 8; j++) unpack2(acc[i][j], vals[2 * i][j], vals[2 * i + 1][j]);

    #pragma unroll
    for (int rr = 0; rr < 8; rr++) {
        int grow = rowBase + ty * 8 + rr;
        int gcol = colBase + tx * 8;
        float o[8];
        #pragma unroll
        for (int j = 0; j < 8; j++) {
            float v = vals[rr][j] + b1[gcol + j];
            o[j] = v > 0.f ? v : 0.f;
        }
        float* dst = g_x + (size_t)grow * EMB + gcol;
        *(float4*)(dst)     = make_float4(o[0], o[1], o[2], o[3]);
        *(float4*)(dst + 4) = make_float4(o[4], o[5], o[6], o[7]);
    }
}

// ---------------------------------------------------------------------------
// K2: gate-interleaved GEMM2 + LSTM epilogue.
// Block covers 128 batch rows x 32 hid cols (= 128 gate columns).
// Tile column r (0..127)  <->  W_ih row = 512*(r%4) + hb + r/4, so each
// thread's 8 contiguous columns = 2 hid indices x all 4 gates {i,f,g,o}.
// ---------------------------------------------------------------------------
__global__ void __launch_bounds__(256) lstm_kernel(
    const float* __restrict__ Wih, const float* __restrict__ cell,
    float* __restrict__ out)
{
    __shared__ float As[16][128];
    __shared__ float Ws[16][128];
    const int tid = threadIdx.x;
    const int ty = tid >> 4, tx = tid & 15;
    const int rowBase = blockIdx.x * 128;
    const int hb = blockIdx.y * 32;
    const int lr = tid >> 2;
    const int lc = (tid & 3) * 4;

    ull acc[4][8];
    #pragma unroll
    for (int i = 0; i < 4; i++)
        #pragma unroll
        for (int j = 0; j < 8; j++) acc[i][j] = 0ULL;

    for (int k0 = 0; k0 < EMB; k0 += 16) {
        #pragma unroll
        for (int hh = 0; hh < 2; hh++) {
            int r = lr + hh * 64;
            float4 av = *(const float4*)(g_x + (size_t)(rowBase + r) * EMB + k0 + lc);
            As[lc + 0][r] = av.x; As[lc + 1][r] = av.y;
            As[lc + 2][r] = av.z; As[lc + 3][r] = av.w;
            int wrow = ((r & 3) << 9) + hb + (r >> 2);   // 512*gate + hid
            float4 wv = *(const float4*)(Wih + (size_t)wrow * EMB + k0 + lc);
            Ws[lc + 0][r] = wv.x; Ws[lc + 1][r] = wv.y;
            Ws[lc + 2][r] = wv.z; Ws[lc + 3][r] = wv.w;
        }
        __syncthreads();
        #pragma unroll
        for (int kk = 0; kk < 16; kk++) {
            ulonglong2 a01 = *(const ulonglong2*)&As[kk][ty * 8];
            ulonglong2 a23 = *(const ulonglong2*)&As[kk][ty * 8 + 4];
            ull a2v[4] = {a01.x, a01.y, a23.x, a23.y};
            float4 b0  = *(const float4*)&Ws[kk][tx * 8];
            float4 b1v = *(const float4*)&Ws[kk][tx * 8 + 4];
            float bb[8] = {b0.x, b0.y, b0.z, b0.w, b1v.x, b1v.y, b1v.z, b1v.w};
            #pragma unroll
            for (int j = 0; j < 8; j++) {
                ull bd = pack2(bb[j], bb[j]);
                #pragma unroll
                for (int i = 0; i < 4; i++) acc[i][j] = ffma2(a2v[i], bd, acc[i][j]);
            }
        }
        __syncthreads();
    }

    float vals[8][8];
    #pragma unroll
    for (int i = 0; i < 4; i++)
        #pragma unroll
        for (int j = 0; j < 8; j++) unpack2(acc[i][j], vals[2 * i][j], vals[2 * i + 1][j]);

    #pragma unroll
    for (int rr = 0; rr < 8; rr++) {
        int grow = rowBase + ty * 8 + rr;
        #pragma unroll
        for (int jh = 0; jh < 2; jh++) {
            int hid = hb + tx * 2 + jh;            // global hid index
            // column j = jh*4 + gate; gate order i,f,g,o (torch LSTMCell)
            float iv = sigmoidf_(vals[rr][jh * 4 + 0] + g_hvec[hid]);
            float fv = sigmoidf_(vals[rr][jh * 4 + 1] + g_hvec[HID + hid]);
            float gv = tanhf_   (vals[rr][jh * 4 + 2] + g_hvec[2 * HID + hid]);
            float ov = sigmoidf_(vals[rr][jh * 4 + 3] + g_hvec[3 * HID + hid]);
            float c = fv * cell[hid] + iv * gv;
            float h = ov * tanhf_(c);
            g_h[(size_t)grow * HID + hid] = h;
            if (grow == B_ROWS - 1) {
                out[(size_t)B_ROWS * NQ + hid]       = h;   // h_new[-1]
                out[(size_t)B_ROWS * NQ + HID + hid] = c;   // c_new[-1]
            }
        }
    }
}

// ---------------------------------------------------------------------------
// K3: q = h_new @ W2^T + b2.  Block = 32 rows x 32 cols, chunked K=128.
// ---------------------------------------------------------------------------
__global__ void __launch_bounds__(256) q_kernel(
    const float* __restrict__ W2, const float* __restrict__ b2,
    float* __restrict__ q)
{
    __shared__ float sW[32][129];   // pad -> conflict-free column reads
    __shared__ float sH[32][128];
    const int tid = threadIdx.x;
    const int rowBase = blockIdx.x * 32;
    const int c  = tid & 31;
    const int rq = tid >> 5;        // 0..7
    const int lwr = tid >> 3;       // 0..31
    const int lwc = (tid & 7) * 16; // 0..112

    float acc[4] = {0.f, 0.f, 0.f, 0.f};

    for (int k0 = 0; k0 < HID; k0 += 128) {
        #pragma unroll
        for (int i = 0; i < 4; i++) {
            float4 wv = *(const float4*)(W2 + (size_t)lwr * HID + k0 + lwc + i * 4);
            sW[lwr][lwc + i * 4 + 0] = wv.x; sW[lwr][lwc + i * 4 + 1] = wv.y;
            sW[lwr][lwc + i * 4 + 2] = wv.z; sW[lwr][lwc + i * 4 + 3] = wv.w;
            float4 hv = *(const float4*)(g_h + (size_t)(rowBase + lwr) * HID + k0 + lwc + i * 4);
            sH[lwr][lwc + i * 4 + 0] = hv.x; sH[lwr][lwc + i * 4 + 1] = hv.y;
            sH[lwr][lwc + i * 4 + 2] = hv.z; sH[lwr][lwc + i * 4 + 3] = hv.w;
        }
        __syncthreads();
        #pragma unroll 8
        for (int kk = 0; kk < 128; kk++) {
            float w = sW[c][kk];
            #pragma unroll
            for (int r = 0; r < 4; r++) acc[r] += sH[rq + r * 8][kk] * w;
        }
        __syncthreads();
    }
    #pragma unroll
    for (int r = 0; r < 4; r++)
        q[(size_t)(rowBase + rq + r * 8) * NQ + c] = acc[r] + b2[c];
}

// ---------------------------------------------------------------------------
// Launch. Input order per metadata: observation, prev_action, hidden_state,
// cell_state, W1, b1, W_ih, b_ih, W_hh, b_hh, W2, b2.
// ---------------------------------------------------------------------------
extern "C" void kernel_launch(void* const* d_in, const int* in_sizes, int n_in,
                              void* d_out, int out_size)
{
    const float* obs  = (const float*)d_in[0];
    const float* act  = (const float*)d_in[1];
    const float* hst  = (const float*)d_in[2];
    const float* cst  = (const float*)d_in[3];
    const float* W1   = (const float*)d_in[4];
    const float* b1   = (const float*)d_in[5];
    const float* Wih  = (const float*)d_in[6];
    const float* bih  = (const float*)d_in[7];
    const float* Whh  = (const float*)d_in[8];
    const float* bhh  = (const float*)d_in[9];
    const float* W2   = (const float*)d_in[10];
    const float* b2   = (const float*)d_in[11];
    float* out = (float*)d_out;

    hvec_kernel<<<256, 256>>>(Whh, hst, bih, bhh);
    mlp1_kernel<<<dim3(B_ROWS / 128, EMB / 128), 256>>>(obs, act, W1, b1);
    lstm_kernel<<<dim3(B_ROWS / 128, HID / 32), 256>>>(Wih, cst, out);
    q_kernel<<<B_ROWS / 32, 256>>>(W2, b2, out);
}

// round 7
// speedup vs baseline: 2.4871x; 2.4838x over previous
#include <cuda_runtime.h>
#include <cstdint>

// ---------------------------------------------------------------------------
// DRQN fused pipeline, GB300 (sm_103a, but harness targets base sm_103 —
// tcgen05 unavailable; use legacy mma.sync tf32 on the tensor pipe).
//
//   hvec   = W_hh @ h + b_ih + b_hh                     (vector, 2048)
//   x      = relu([obs|act] @ W1^T + b1)                (GEMM1, mma.sync tf32)
//   gates  = x @ Wih^T (gate-interleaved) + hvec -> LSTM (GEMM2 + fused cell)
//   q      = h_new @ W2^T + b2                          (GEMM3)
//
// Output: [ q (B*32) | h_new[B-1] (512) | c_new[B-1] (512) ]
// ---------------------------------------------------------------------------

#define B_ROWS 32768
#define OBS    512
#define ACT    32
#define KIN    544
#define EMB    512
#define HID    512
#define NQ     32

__device__ float g_x[(size_t)B_ROWS * EMB];     // 64 MB
__device__ float g_h[(size_t)B_ROWS * HID];     // 64 MB
__device__ float g_hvec[4 * HID];

// ------------------------------ helpers -----------------------------------
__device__ __forceinline__ uint32_t smem_u32(const void* p) {
    uint32_t a;
    asm("{ .reg .u64 t; cvta.to.shared.u64 t, %1; cvt.u32.u64 %0, t; }"
        : "=r"(a) : "l"(p));
    return a;
}
__device__ __forceinline__ uint32_t tf32r(float f) {   // round-to-nearest tf32
    uint32_t u; asm("cvt.rna.tf32.f32 %0, %1;" : "=r"(u) : "f"(f)); return u;
}
__device__ __forceinline__ uint4 tf4(float4 v) {
    return make_uint4(tf32r(v.x), tf32r(v.y), tf32r(v.z), tf32r(v.w));
}
__device__ __forceinline__ void ldsm4(uint32_t* r, uint32_t addr) {
    asm volatile("ldmatrix.sync.aligned.m8n8.x4.shared.b16 {%0,%1,%2,%3}, [%4];"
                 : "=r"(r[0]), "=r"(r[1]), "=r"(r[2]), "=r"(r[3]) : "r"(addr));
}
__device__ __forceinline__ void mma_tf(float* c, const uint32_t* a,
                                       uint32_t b0, uint32_t b1) {
    asm volatile(
        "mma.sync.aligned.m16n8k8.row.col.f32.tf32.tf32.f32 "
        "{%0,%1,%2,%3}, {%4,%5,%6,%7}, {%8,%9}, {%0,%1,%2,%3};"
        : "+f"(c[0]), "+f"(c[1]), "+f"(c[2]), "+f"(c[3])
        : "r"(a[0]), "r"(a[1]), "r"(a[2]), "r"(a[3]), "r"(b0), "r"(b1));
}
__device__ __forceinline__ float sigmoidf_(float x) {
    return __fdividef(1.f, 1.f + __expf(-x));
}
__device__ __forceinline__ float tanhf_(float x) {
    return __fdividef(2.f, 1.f + __expf(-2.f * x)) - 1.f;
}

// ---------------------------------------------------------------------------
// K0: hvec[n] = dot(W_hh[n,:], h) + b_ih[n] + b_hh[n]
// ---------------------------------------------------------------------------
__global__ void __launch_bounds__(256) hvec_kernel(
    const float* __restrict__ Whh, const float* __restrict__ h,
    const float* __restrict__ bih, const float* __restrict__ bhh)
{
    int w    = (blockIdx.x * blockDim.x + threadIdx.x) >> 5;
    int lane = threadIdx.x & 31;
    if (w >= 4 * HID) return;
    const float* row = Whh + (size_t)w * HID;
    float s = 0.f;
    #pragma unroll
    for (int k = 0; k < HID; k += 32) s += row[k + lane] * h[k + lane];
    #pragma unroll
    for (int o = 16; o > 0; o >>= 1) s += __shfl_xor_sync(0xffffffffu, s, o);
    if (lane == 0) g_hvec[w] = s + bih[w] + bhh[w];
}

// ---------------------------------------------------------------------------
// mma.sync tf32 GEMM: BM=128, BN=128, BK=16, 256 thr, warp tile 64x32.
// MODE 0: x = relu([obs|act] @ W1^T + b1)          grid (256, 4)
// MODE 1: gate-interleaved GEMM2 + LSTM cell       grid (256, 16), 32 hid/CTA
//
// smem: [0,1024) aux | [1024, ...) 2 stages of (A 8K | B 8K); epilogue reuses
// the tile region as a staging buffer for coalesced global stores.
// smem bytes: MODE0 68608, MODE1 33792.
// ---------------------------------------------------------------------------
template <int MODE>
__global__ void __launch_bounds__(256, 2) mma_gemm_kernel(
    const float* __restrict__ obs, const float* __restrict__ act,
    const float* __restrict__ W1,  const float* __restrict__ b1,
    const float* __restrict__ Wih, const float* __restrict__ cell,
    float* __restrict__ out)
{
    extern __shared__ char smem[];
    float* s_aux = (float*)smem;            // MODE0: bias[128]; MODE1: cell[32]+hvec[4][32]
    char*  tiles = smem + 1024;
    float* s_epi = (float*)(smem + 1024);

    const int tid  = threadIdx.x;
    const int lane = tid & 31;
    const int wid  = tid >> 5;
    const int warp_m = wid & 1, warp_n = wid >> 1;
    const int m0w = warp_m * 64, n0w = warp_n * 32;
    const int rowBase = blockIdx.x * 128;
    const int colBase = blockIdx.y * 128;   // MODE 0
    const int hb      = blockIdx.y * 32;    // MODE 1

    if (MODE == 0) {
        if (tid < 128) s_aux[tid] = b1[colBase + tid];
    } else {
        if (tid < 32)  s_aux[tid] = cell[hb + tid];
        if (tid < 128) s_aux[32 + tid] = g_hvec[((tid >> 5) << 9) + hb + (tid & 31)];
    }

    const uint32_t tiles_u = smem_u32(tiles);

    // g2s: 512 16B chunks per operand tile; 2 per thread
    const int mL0 = tid >> 2,         cL0 = tid & 3;
    const int mL1 = (tid + 256) >> 2, cL1 = (tid + 256) & 3;

    // ldmatrix per-lane constants
    const int a_m  = m0w + (lane & 15);
    const int a_cb = lane >> 4;
    const int a_sw = a_m & 3;
    const int b_n  = n0w + (lane & 7) + ((lane & 16) >> 1);
    const int b_cb = (lane >> 3) & 1;

    const int KT = (MODE == 0) ? KIN / 16 : EMB / 16;

    float acc[4][4][4];
    #pragma unroll
    for (int i = 0; i < 4; i++)
        #pragma unroll
        for (int j = 0; j < 4; j++)
            #pragma unroll
            for (int k = 0; k < 4; k++) acc[i][j][k] = 0.f;

    float4 ra[2], rb[2];

    auto ldg = [&](int t) {
        const int k0 = t * 16;
        #pragma unroll
        for (int j = 0; j < 2; j++) {
            int m = j ? mL1 : mL0, c = j ? cL1 : cL0;
            int k = k0 + 4 * c;
            const float* ap;
            if (MODE == 0)
                ap = (k < OBS) ? obs + (size_t)(rowBase + m) * OBS + k
                               : act + (size_t)(rowBase + m) * ACT + (k - OBS);
            else
                ap = g_x + (size_t)(rowBase + m) * EMB + k;
            ra[j] = *(const float4*)ap;
            const float* bp;
            if (MODE == 0) {
                bp = W1 + (size_t)(colBase + m) * KIN + k;
            } else {
                int wr = ((m & 3) << 9) + hb + (m >> 2);   // 512*gate + hid
                bp = Wih + (size_t)wr * EMB + k;
            }
            rb[j] = *(const float4*)bp;
        }
    };
    auto sts = [&](int s) {
        char* sa = tiles + s * 16384;
        char* sb = sa + 8192;
        #pragma unroll
        for (int j = 0; j < 2; j++) {
            int m = j ? mL1 : mL0, c = j ? cL1 : cL0;
            int off = m * 64 + ((c ^ (m & 3)) << 4);   // swizzled 16B chunk
            *(uint4*)(sa + off) = tf4(ra[j]);
            *(uint4*)(sb + off) = tf4(rb[j]);
        }
    };
    auto compute = [&](int s) {
        const uint32_t Ab = tiles_u + s * 16384;
        const uint32_t Bb = Ab + 8192;
        #pragma unroll
        for (int ks = 0; ks < 2; ks++) {
            uint32_t af[4][4], bf[2][4];
            #pragma unroll
            for (int mi = 0; mi < 4; mi++) {
                int m = a_m + 16 * mi;
                ldsm4(af[mi], Ab + m * 64 + (((2 * ks + a_cb) ^ a_sw) << 4));
            }
            #pragma unroll
            for (int p = 0; p < 2; p++) {
                int n = b_n + 16 * p;
                ldsm4(bf[p], Bb + n * 64 + (((2 * ks + b_cb) ^ (n & 3)) << 4));
            }
            #pragma unroll
            for (int mi = 0; mi < 4; mi++)
                #pragma unroll
                for (int ni = 0; ni < 4; ni++)
                    mma_tf(acc[mi][ni], af[mi],
                           bf[ni >> 1][(ni & 1) * 2], bf[ni >> 1][(ni & 1) * 2 + 1]);
        }
    };

    ldg(0); sts(0); __syncthreads();
    for (int t = 0; t < KT; t++) {
        if (t + 1 < KT) ldg(t + 1);
        compute(t & 1);
        if (t + 1 < KT) sts((t + 1) & 1);
        __syncthreads();
    }

    // ---------------- epilogue (smem-staged, coalesced stores) -------------
    if (MODE == 0) {
        #pragma unroll
        for (int mi = 0; mi < 4; mi++) {
            int r = m0w + 16 * mi + (lane >> 2);
            #pragma unroll
            for (int ni = 0; ni < 4; ni++) {
                int col = n0w + 8 * ni + 2 * (lane & 3);
                *(float2*)&s_epi[r * 132 + col] =
                    make_float2(acc[mi][ni][0], acc[mi][ni][1]);
                *(float2*)&s_epi[(r + 8) * 132 + col] =
                    make_float2(acc[mi][ni][2], acc[mi][ni][3]);
            }
        }
        __syncthreads();
        #pragma unroll
        for (int i = 0; i < 16; i++) {
            int id = tid + 256 * i;
            int r = id >> 5, c4 = (id & 31) * 4;
            float4 v = *(float4*)&s_epi[r * 132 + c4];
            v.x = fmaxf(v.x + s_aux[c4 + 0], 0.f);
            v.y = fmaxf(v.y + s_aux[c4 + 1], 0.f);
            v.z = fmaxf(v.z + s_aux[c4 + 2], 0.f);
            v.w = fmaxf(v.w + s_aux[c4 + 3], 0.f);
            *(float4*)(g_x + (size_t)(rowBase + r) * EMB + colBase + c4) = v;
        }
    } else {
        // gates land pairwise across lane pairs: even t4 holds (i,f), odd (g,o)
        #pragma unroll
        for (int mi = 0; mi < 4; mi++) {
            #pragma unroll
            for (int ni = 0; ni < 4; ni++) {
                float c0 = acc[mi][ni][0], c1 = acc[mi][ni][1];
                float c2 = acc[mi][ni][2], c3 = acc[mi][ni][3];
                float e0 = __shfl_xor_sync(0xffffffffu, c0, 1);
                float e1 = __shfl_xor_sync(0xffffffffu, c1, 1);
                float e2 = __shfl_xor_sync(0xffffffffu, c2, 1);
                float e3 = __shfl_xor_sync(0xffffffffu, c3, 1);
                bool ev = !(lane & 1);
                int rl = m0w + 16 * mi + (lane >> 2) + (ev ? 0 : 8);
                float gi = ev ? c0 : e2;
                float gf = ev ? c1 : e3;
                float gg = ev ? e0 : c2;
                float go = ev ? e1 : c3;
                int hl = (n0w >> 2) + 2 * ni + ((lane & 3) >> 1);
                float iv = sigmoidf_(gi + s_aux[32 + hl]);
                float fv = sigmoidf_(gf + s_aux[64 + hl]);
                float gv = tanhf_   (gg + s_aux[96 + hl]);
                float ov = sigmoidf_(go + s_aux[128 + hl]);
                float cn = fv * s_aux[hl] + iv * gv;
                float hn = ov * tanhf_(cn);
                s_epi[rl * 36 + hl] = hn;
                if (rowBase + rl == B_ROWS - 1) {
                    out[(size_t)B_ROWS * NQ + hb + hl]       = hn;
                    out[(size_t)B_ROWS * NQ + HID + hb + hl] = cn;
                }
            }
        }
        __syncthreads();
        #pragma unroll
        for (int i = 0; i < 4; i++) {
            int id = tid + 256 * i;
            int r = id >> 3, c4 = (id & 7) * 4;
            float4 v = *(float4*)&s_epi[r * 36 + c4];
            *(float4*)(g_h + (size_t)(rowBase + r) * HID + hb + c4) = v;
        }
    }
}

// ---------------------------------------------------------------------------
// K3: q = h_new @ W2^T + b2. 32 rows x 32 cols per CTA, float4 inner loop.
// ---------------------------------------------------------------------------
__global__ void __launch_bounds__(256) q_kernel(
    const float* __restrict__ W2, const float* __restrict__ b2,
    float* __restrict__ q)
{
    __shared__ float4 sWT[32][32];    // [k4][c] = W2[c][ko + 4*k4 ..]
    __shared__ float4 sH4[32][33];    // [row][k4]
    const int tid = threadIdx.x;
    const int rowBase = blockIdx.x * 32;
    const int c = tid & 31, rq = tid >> 5;
    float acc[4] = {0.f, 0.f, 0.f, 0.f};

    for (int ko = 0; ko < HID; ko += 128) {
        #pragma unroll
        for (int i = 0; i < 4; i++) {
            int idx = tid + (i << 8);
            int a = idx >> 5, bcol = idx & 31;
            sWT[a][bcol] = *(const float4*)(W2 + (size_t)bcol * HID + ko + (a << 2));
            sH4[a][bcol] = *(const float4*)(g_h + (size_t)(rowBase + a) * HID + ko + (bcol << 2));
        }
        __syncthreads();
        #pragma unroll 8
        for (int k4 = 0; k4 < 32; k4++) {
            float4 w = sWT[k4][c];
            #pragma unroll
            for (int r = 0; r < 4; r++) {
                float4 h = sH4[rq + (r << 3)][k4];
                acc[r] += w.x * h.x + w.y * h.y + w.z * h.z + w.w * h.w;
            }
        }
        __syncthreads();
    }
    #pragma unroll
    for (int r = 0; r < 4; r++)
        q[(size_t)(rowBase + rq + (r << 3)) * NQ + c] = acc[r] + b2[c];
}

// ---------------------------------------------------------------------------
extern "C" void kernel_launch(void* const* d_in, const int* in_sizes, int n_in,
                              void* d_out, int out_size)
{
    const float* obs = (const float*)d_in[0];
    const float* act = (const float*)d_in[1];
    const float* hst = (const float*)d_in[2];
    const float* cst = (const float*)d_in[3];
    const float* W1  = (const float*)d_in[4];
    const float* b1  = (const float*)d_in[5];
    const float* Wih = (const float*)d_in[6];
    const float* bih = (const float*)d_in[7];
    const float* Whh = (const float*)d_in[8];
    const float* bhh = (const float*)d_in[9];
    const float* W2  = (const float*)d_in[10];
    const float* b2  = (const float*)d_in[11];
    float* out = (float*)d_out;

    const int SMEM0 = 1024 + 128 * 132 * 4;   // 68608 (epilogue stage dominates)
    const int SMEM1 = 1024 + 2 * 16384;       // 33792
    cudaFuncSetAttribute(mma_gemm_kernel<0>,
                         cudaFuncAttributeMaxDynamicSharedMemorySize, SMEM0);
    cudaFuncSetAttribute(mma_gemm_kernel<1>,
                         cudaFuncAttributeMaxDynamicSharedMemorySize, SMEM1);

    hvec_kernel<<<256, 256>>>(Whh, hst, bih, bhh);
    mma_gemm_kernel<0><<<dim3(B_ROWS / 128, EMB / 128), 256, SMEM0>>>(
        obs, act, W1, b1, Wih, cst, out);
    mma_gemm_kernel<1><<<dim3(B_ROWS / 128, HID / 32), 256, SMEM1>>>(
        obs, act, W1, b1, Wih, cst, out);
    q_kernel<<<B_ROWS / 32, 256>>>(W2, b2, out);
}

// round 9
// speedup vs baseline: 3.2987x; 1.3263x over previous
#include <cuda_runtime.h>
#include <cstdint>

// ---------------------------------------------------------------------------
// DRQN fused pipeline (sm_103 base ISA: legacy mma.sync tf32 + cp.async).
// All GEMM operands pre-rounded to tf32 (cvt.rna) once -> mainloops are pure
// LDGSTS/LDSM/HMMA with 4-stage pipelines.
//
// NOTE: __device__ globals (g_in/g_x/g_h/g_w*) are ONLY referenced from
// device code. Passing them as host-side kernel args binds the host shadow
// (silently readable on GB300 via ATS) -> round-8 bug.
//
//   hvec = W_hh@h + b_ih + b_hh
//   x    = relu(g_in @ W1^T + b1)        GEMM1 BM128 BN256 (x stored tf32)
//   gates= x @ Wih^T (gate-interleaved) -> LSTM cell      GEMM2 BM128 BN256
//   q    = h @ W2^T + b2                 GEMM3 BM128 BN32 (mma)
// Output: [ q (B*32) | h_new[B-1] (512) | c_new[B-1] (512) ]
// ---------------------------------------------------------------------------

#define B_ROWS 32768
#define OBS    512
#define ACT    32
#define KIN    544
#define EMB    512
#define HID    512
#define NQ     32

__device__ float g_in[(size_t)B_ROWS * KIN];    // 71 MB packed+rounded input
__device__ float g_x [(size_t)B_ROWS * EMB];    // 64 MB (tf32-rounded)
__device__ float g_h [(size_t)B_ROWS * HID];    // 64 MB (tf32-rounded)
__device__ float g_w1 [EMB * KIN];
__device__ float g_wih[4 * HID * EMB];
__device__ float g_w2 [NQ * HID];
__device__ float g_hvec[4 * HID];

// ------------------------------ helpers -----------------------------------
__device__ __forceinline__ uint32_t smem_u32(const void* p) {
    uint32_t a;
    asm("{ .reg .u64 t; cvta.to.shared.u64 t, %1; cvt.u32.u64 %0, t; }"
        : "=r"(a) : "l"(p));
    return a;
}
__device__ __forceinline__ uint32_t tf32r(float f) {
    uint32_t u; asm("cvt.rna.tf32.f32 %0, %1;" : "=r"(u) : "f"(f)); return u;
}
__device__ __forceinline__ float tf32f(float f) { return __uint_as_float(tf32r(f)); }
__device__ __forceinline__ float4 r4(float4 v) {
    v.x = tf32f(v.x); v.y = tf32f(v.y); v.z = tf32f(v.z); v.w = tf32f(v.w);
    return v;
}
__device__ __forceinline__ void ldsm4(uint32_t* r, uint32_t addr) {
    asm volatile("ldmatrix.sync.aligned.m8n8.x4.shared.b16 {%0,%1,%2,%3}, [%4];"
                 : "=r"(r[0]), "=r"(r[1]), "=r"(r[2]), "=r"(r[3]) : "r"(addr));
}
__device__ __forceinline__ void mma_tf(float* c, const uint32_t* a,
                                       uint32_t b0, uint32_t b1) {
    asm volatile(
        "mma.sync.aligned.m16n8k8.row.col.f32.tf32.tf32.f32 "
        "{%0,%1,%2,%3}, {%4,%5,%6,%7}, {%8,%9}, {%0,%1,%2,%3};"
        : "+f"(c[0]), "+f"(c[1]), "+f"(c[2]), "+f"(c[3])
        : "r"(a[0]), "r"(a[1]), "r"(a[2]), "r"(a[3]), "r"(b0), "r"(b1));
}
#define CP16(dst, src) asm volatile("cp.async.cg.shared.global [%0], [%1], 16;" :: "r"(dst), "l"(src) : "memory")
#define CP_COMMIT()    asm volatile("cp.async.commit_group;" ::: "memory")
#define CP_WAIT2()     asm volatile("cp.async.wait_group 2;" ::: "memory")

__device__ __forceinline__ float sigmoidf_(float x) {
    return __fdividef(1.f, 1.f + __expf(-x));
}
__device__ __forceinline__ float tanhf_(float x) {
    return __fdividef(2.f, 1.f + __expf(-2.f * x)) - 1.f;
}

// ---------------------------------------------------------------------------
// Pre-pass: pack [obs|act] rounded into g_in; round weight copies.
// ---------------------------------------------------------------------------
__global__ void __launch_bounds__(256) pack_in_kernel(
    const float* __restrict__ obs, const float* __restrict__ act)
{
    int id = blockIdx.x * 256 + threadIdx.x;           // over B_ROWS*136 float4
    if (id >= B_ROWS * 136) return;
    int b = id / 136, c4 = (id - b * 136) * 4;
    float4 v = (c4 < OBS) ? *(const float4*)(obs + (size_t)b * OBS + c4)
                          : *(const float4*)(act + (size_t)b * ACT + (c4 - OBS));
    *(float4*)(g_in + (size_t)b * KIN + c4) = r4(v);
}
__global__ void __launch_bounds__(256) conv_w_kernel(
    const float* __restrict__ W1, const float* __restrict__ Wih,
    const float* __restrict__ W2)
{
    int id = blockIdx.x * 256 + threadIdx.x;           // float4 index
    const int N1 = EMB * KIN / 4, N2 = N1 + 4 * HID * EMB / 4;
    const int N3 = N2 + NQ * HID / 4;
    if (id < N1)      *(float4*)(g_w1  + 4 * id)        = r4(*(const float4*)(W1  + 4 * id));
    else if (id < N2) *(float4*)(g_wih + 4 * (id - N1)) = r4(*(const float4*)(Wih + 4 * (size_t)(id - N1)));
    else if (id < N3) *(float4*)(g_w2  + 4 * (id - N2)) = r4(*(const float4*)(W2  + 4 * (id - N2)));
}

// ---------------------------------------------------------------------------
// K0: hvec[n] = dot(W_hh[n,:], h) + b_ih[n] + b_hh[n]   (exact fp32)
// ---------------------------------------------------------------------------
__global__ void __launch_bounds__(256) hvec_kernel(
    const float* __restrict__ Whh, const float* __restrict__ h,
    const float* __restrict__ bih, const float* __restrict__ bhh)
{
    int w    = (blockIdx.x * blockDim.x + threadIdx.x) >> 5;
    int lane = threadIdx.x & 31;
    if (w >= 4 * HID) return;
    const float* row = Whh + (size_t)w * HID;
    float s = 0.f;
    #pragma unroll
    for (int k = 0; k < HID; k += 32) s += row[k + lane] * h[k + lane];
    #pragma unroll
    for (int o = 16; o > 0; o >>= 1) s += __shfl_xor_sync(0xffffffffu, s, o);
    if (lane == 0) g_hvec[w] = s + bih[w] + bhh[w];
}

// ---------------------------------------------------------------------------
// GEMM: BM=128, BN=256, BK=16, 256 thr (8 warps, warp tile 64x64), 4 stages.
// MODE 0: x = relu(g_in @ g_w1^T + b1)     grid (2, 256)
// MODE 1: gate-interleaved + LSTM cell     grid (8, 256), 64 hid/CTA
// smem: [0,2048) aux | 4 stages x (A 8K | B 16K); MODE1 epilogue reuses tiles.
// ---------------------------------------------------------------------------
#define NS 4
#define STG 24576
#define GSMEM (2048 + NS * STG)      // 100352

template <int MODE>
__global__ void __launch_bounds__(256, 1) mma_gemm_kernel(
    const float* __restrict__ b1, const float* __restrict__ cell,
    float* __restrict__ out)
{
    constexpr int KA = (MODE == 0) ? KIN : EMB;
    constexpr int KT = KA / 16;
    // Device-side binding of the scratch globals (NEVER pass these from host).
    const float* gA = (MODE == 0) ? g_in : g_x;
    const float* gB = (MODE == 0) ? g_w1 : g_wih;

    extern __shared__ char smem[];
    float* s_aux = (float*)smem;
    char*  tiles = smem + 2048;
    float* s_epi = (float*)tiles;
    const uint32_t tiles_u = smem_u32(tiles);

    const int tid = threadIdx.x, lane = tid & 31, wid = tid >> 5;
    const int m0w = 64 * (wid & 1), n0w = 64 * (wid >> 1);
    const int rowBase = blockIdx.y * 128;
    const int colBase = blockIdx.x * 256;   // MODE 0
    const int hb      = blockIdx.x * 64;    // MODE 1

    if (MODE == 0) {
        s_aux[tid] = b1[colBase + tid];
    } else {
        if (tid < 64) s_aux[tid] = cell[hb + tid];
        s_aux[64 + tid] = g_hvec[((tid >> 6) << 9) + hb + (tid & 63)];
    }

    // ---- cp.async source pointers / smem offsets (constant per thread) ----
    const char* aptr[2]; uint32_t aoff[2];
    #pragma unroll
    for (int j = 0; j < 2; j++) {
        int m = (tid + 256 * j) >> 2, c = tid & 3;
        aptr[j] = (const char*)(gA + (size_t)(rowBase + m) * KA + 4 * c);
        aoff[j] = m * 64 + ((c ^ (m & 3)) << 4);
    }
    const char* bptr[4]; uint32_t boff[4];
    #pragma unroll
    for (int j = 0; j < 4; j++) {
        int id = tid + 256 * j;
        int r = id >> 2, c = id & 3;
        if (MODE == 0) {
            bptr[j] = (const char*)(gB + (size_t)(colBase + r) * KA + 4 * c);
        } else {
            int wr = ((r & 3) << 9) + hb + (r >> 2);    // 512*gate + hid
            bptr[j] = (const char*)(gB + (size_t)wr * EMB + 4 * c);
        }
        boff[j] = 8192 + r * 64 + ((c ^ (r & 3)) << 4);
    }

    // ldmatrix lane constants
    const int a_m  = m0w + (lane & 15);
    const int a_cb = lane >> 4, a_sw = a_m & 3;
    const int b_n  = n0w + (lane & 7) + ((lane & 16) >> 1);
    const int b_cb = (lane >> 3) & 1, b_sw = b_n & 3;

    float acc[4][8][4];
    #pragma unroll
    for (int i = 0; i < 4; i++)
        #pragma unroll
        for (int j = 0; j < 8; j++)
            #pragma unroll
            for (int k = 0; k < 4; k++) acc[i][j][k] = 0.f;

    auto issue = [&](int t) {
        uint32_t base = tiles_u + (t & (NS - 1)) * STG;
        size_t ko = (size_t)t * 64;
        #pragma unroll
        for (int j = 0; j < 2; j++) CP16(base + aoff[j], aptr[j] + ko);
        #pragma unroll
        for (int j = 0; j < 4; j++) CP16(base + boff[j], bptr[j] + ko);
        CP_COMMIT();
    };
    auto compute = [&](int s) {
        const uint32_t Ab = tiles_u + s * STG, Bb = Ab + 8192;
        #pragma unroll
        for (int ks = 0; ks < 2; ks++) {
            uint32_t af[4][4], bf[4][4];
            #pragma unroll
            for (int mi = 0; mi < 4; mi++)
                ldsm4(af[mi], Ab + (a_m + 16 * mi) * 64 + (((2 * ks + a_cb) ^ a_sw) << 4));
            #pragma unroll
            for (int p = 0; p < 4; p++)
                ldsm4(bf[p], Bb + (b_n + 16 * p) * 64 + (((2 * ks + b_cb) ^ b_sw) << 4));
            #pragma unroll
            for (int mi = 0; mi < 4; mi++)
                #pragma unroll
                for (int ni = 0; ni < 8; ni++)
                    mma_tf(acc[mi][ni], af[mi],
                           bf[ni >> 1][(ni & 1) * 2], bf[ni >> 1][(ni & 1) * 2 + 1]);
        }
    };

    issue(0); issue(1); issue(2);
    for (int t = 0; t < KT; t++) {
        CP_WAIT2();
        __syncthreads();
        compute(t & (NS - 1));
        if (t + 3 < KT) issue(t + 3); else CP_COMMIT();   // keep group count
    }

    // ---------------- epilogue ----------------
    if (MODE == 0) {
        #pragma unroll
        for (int mi = 0; mi < 4; mi++) {
            int r = rowBase + m0w + 16 * mi + (lane >> 2);
            #pragma unroll
            for (int ni = 0; ni < 8; ni++) {
                int cl = n0w + 8 * ni + 2 * (lane & 3);
                float* d0 = g_x + (size_t)r * EMB + colBase + cl;
                *(float2*)d0 = make_float2(
                    tf32f(fmaxf(acc[mi][ni][0] + s_aux[cl], 0.f)),
                    tf32f(fmaxf(acc[mi][ni][1] + s_aux[cl + 1], 0.f)));
                *(float2*)(d0 + 8 * EMB) = make_float2(
                    tf32f(fmaxf(acc[mi][ni][2] + s_aux[cl], 0.f)),
                    tf32f(fmaxf(acc[mi][ni][3] + s_aux[cl + 1], 0.f)));
            }
        }
    } else {
        __syncthreads();                        // tiles -> s_epi reuse
        #pragma unroll
        for (int mi = 0; mi < 4; mi++) {
            #pragma unroll
            for (int ni = 0; ni < 8; ni++) {
                float c0 = acc[mi][ni][0], c1 = acc[mi][ni][1];
                float c2 = acc[mi][ni][2], c3 = acc[mi][ni][3];
                float e0 = __shfl_xor_sync(0xffffffffu, c0, 1);
                float e1 = __shfl_xor_sync(0xffffffffu, c1, 1);
                float e2 = __shfl_xor_sync(0xffffffffu, c2, 1);
                float e3 = __shfl_xor_sync(0xffffffffu, c3, 1);
                bool ev = !(lane & 1);
                int rl = m0w + 16 * mi + (lane >> 2) + (ev ? 0 : 8);
                float gi = ev ? c0 : e2;
                float gf = ev ? c1 : e3;
                float gg = ev ? e0 : c2;
                float go = ev ? e1 : c3;
                int hl = (n0w >> 2) + 2 * ni + ((lane & 3) >> 1);
                float iv = sigmoidf_(gi + s_aux[64 + hl]);
                float fv = sigmoidf_(gf + s_aux[128 + hl]);
                float gv = tanhf_   (gg + s_aux[192 + hl]);
                float ov = sigmoidf_(go + s_aux[256 + hl]);
                float cn = fv * s_aux[hl] + iv * gv;
                float hn = ov * tanhf_(cn);
                s_epi[rl * 68 + hl] = tf32f(hn);
                if (rowBase + rl == B_ROWS - 1) {
                    out[(size_t)B_ROWS * NQ + hb + hl]       = hn;
                    out[(size_t)B_ROWS * NQ + HID + hb + hl] = cn;
                }
            }
        }
        __syncthreads();
        #pragma unroll
        for (int i = 0; i < 8; i++) {
            int id = tid + 256 * i;
            int r = id >> 4, c4 = (id & 15) * 4;
            float4 v = *(float4*)&s_epi[r * 68 + c4];
            *(float4*)(g_h + (size_t)(rowBase + r) * HID + hb + c4) = v;
        }
    }
}

// ---------------------------------------------------------------------------
// GEMM3: q = g_h @ g_w2^T + b2. BM=128, BN=32, 128 thr (4 warps, 64x16), 4 st.
// ---------------------------------------------------------------------------
#define QSTG 10240
#define QSMEM (NS * QSTG)            // 40960

__global__ void __launch_bounds__(128) q_mma_kernel(
    const float* __restrict__ b2, float* __restrict__ q)
{
    extern __shared__ char smem[];
    const uint32_t tiles_u = smem_u32(smem);
    const int tid = threadIdx.x, lane = tid & 31, wid = tid >> 5;
    const int m0w = 64 * (wid & 1), n0w = 16 * (wid >> 1);
    const int rowBase = blockIdx.x * 128;

    const char* aptr[4]; uint32_t aoff[4];
    #pragma unroll
    for (int j = 0; j < 4; j++) {
        int m = (tid + 128 * j) >> 2, c = tid & 3;
        aptr[j] = (const char*)(g_h + (size_t)(rowBase + m) * HID + 4 * c);
        aoff[j] = m * 64 + ((c ^ (m & 3)) << 4);
    }
    const int br = tid >> 2, bc = tid & 3;
    const char* bptr = (const char*)(g_w2 + (size_t)br * HID + 4 * bc);
    const uint32_t boff = 8192 + br * 64 + ((bc ^ (br & 3)) << 4);

    const int a_m  = m0w + (lane & 15);
    const int a_cb = lane >> 4, a_sw = a_m & 3;
    const int b_n  = n0w + (lane & 7) + ((lane & 16) >> 1);
    const int b_cb = (lane >> 3) & 1, b_sw = b_n & 3;

    float acc[4][2][4];
    #pragma unroll
    for (int i = 0; i < 4; i++)
        #pragma unroll
        for (int j = 0; j < 2; j++)
            #pragma unroll
            for (int k = 0; k < 4; k++) acc[i][j][k] = 0.f;

    auto issue = [&](int t) {
        uint32_t base = tiles_u + (t & (NS - 1)) * QSTG;
        size_t ko = (size_t)t * 64;
        #pragma unroll
        for (int j = 0; j < 4; j++) CP16(base + aoff[j], aptr[j] + ko);
        CP16(base + boff, bptr + ko);
        CP_COMMIT();
    };

    issue(0); issue(1); issue(2);
    const int KT = HID / 16;
    for (int t = 0; t < KT; t++) {
        CP_WAIT2();
        __syncthreads();
        const uint32_t Ab = tiles_u + (t & (NS - 1)) * QSTG, Bb = Ab + 8192;
        #pragma unroll
        for (int ks = 0; ks < 2; ks++) {
            uint32_t af[4][4], bf[4];
            #pragma unroll
            for (int mi = 0; mi < 4; mi++)
                ldsm4(af[mi], Ab + (a_m + 16 * mi) * 64 + (((2 * ks + a_cb) ^ a_sw) << 4));
            ldsm4(bf, Bb + b_n * 64 + (((2 * ks + b_cb) ^ b_sw) << 4));
            #pragma unroll
            for (int mi = 0; mi < 4; mi++)
                #pragma unroll
                for (int ni = 0; ni < 2; ni++)
                    mma_tf(acc[mi][ni], af[mi], bf[ni * 2], bf[ni * 2 + 1]);
        }
        if (t + 3 < KT) issue(t + 3); else CP_COMMIT();
    }

    #pragma unroll
    for (int mi = 0; mi < 4; mi++) {
        int r = rowBase + m0w + 16 * mi + (lane >> 2);
        #pragma unroll
        for (int ni = 0; ni < 2; ni++) {
            int cl = n0w + 8 * ni + 2 * (lane & 3);
            float bb0 = __ldg(b2 + cl), bb1 = __ldg(b2 + cl + 1);
            float* d0 = q + (size_t)r * NQ + cl;
            *(float2*)d0 = make_float2(acc[mi][ni][0] + bb0, acc[mi][ni][1] + bb1);
            *(float2*)(d0 + 8 * NQ) = make_float2(acc[mi][ni][2] + bb0, acc[mi][ni][3] + bb1);
        }
    }
}

// ---------------------------------------------------------------------------
extern "C" void kernel_launch(void* const* d_in, const int* in_sizes, int n_in,
                              void* d_out, int out_size)
{
    const float* obs = (const float*)d_in[0];
    const float* act = (const float*)d_in[1];
    const float* hst = (const float*)d_in[2];
    const float* cst = (const float*)d_in[3];
    const float* W1  = (const float*)d_in[4];
    const float* b1  = (const float*)d_in[5];
    const float* Wih = (const float*)d_in[6];
    const float* bih = (const float*)d_in[7];
    const float* Whh = (const float*)d_in[8];
    const float* bhh = (const float*)d_in[9];
    const float* W2  = (const float*)d_in[10];
    const float* b2  = (const float*)d_in[11];
    float* out = (float*)d_out;

    cudaFuncSetAttribute(mma_gemm_kernel<0>,
                         cudaFuncAttributeMaxDynamicSharedMemorySize, GSMEM);
    cudaFuncSetAttribute(mma_gemm_kernel<1>,
                         cudaFuncAttributeMaxDynamicSharedMemorySize, GSMEM);
    cudaFuncSetAttribute(q_mma_kernel,
                         cudaFuncAttributeMaxDynamicSharedMemorySize, QSMEM);

    pack_in_kernel<<<(B_ROWS * 136 + 255) / 256, 256>>>(obs, act);
    conv_w_kernel<<<(EMB * KIN / 4 + 4 * HID * EMB / 4 + NQ * HID / 4 + 255) / 256, 256>>>(
        W1, Wih, W2);
    hvec_kernel<<<256, 256>>>(Whh, hst, bih, bhh);

    // x = relu(g_in @ g_w1^T + b1)
    mma_gemm_kernel<0><<<dim3(EMB / 256, B_ROWS / 128), 256, GSMEM>>>(b1, cst, out);
    // gates + LSTM cell
    mma_gemm_kernel<1><<<dim3(4 * HID / 256, B_ROWS / 128), 256, GSMEM>>>(b1, cst, out);
    // q
    q_mma_kernel<<<B_ROWS / 128, 128, QSMEM>>>(b2, out);
}